// round 2
// baseline (speedup 1.0000x reference)
#include <cuda_runtime.h>

// ---------------------------------------------------------------------------
// SKConv2d: out = im2col(x) @ W_eff + 2*bias, where
//   W_eff[d,o] = (1/T) * sum_t ( S1s[t] @ U1s[t] + U2s[t]^T @ S2s[t] )
// Shapes: x[32,128,56,56], W_eff[1152,256], out[32,256,56,56]
// Kernel 1 builds W_eff (row-permuted to (tap, c) ordering) into g_W.
// Kernel 2 is a double-buffered fp32 implicit-GEMM 3x3 conv.
// ---------------------------------------------------------------------------

#define Bb   32
#define Cc   128
#define HH   56
#define WW   56
#define OO   256
#define Dd   1152
#define PLANE (HH*WW)        // 3136
#define NN   (Bb*PLANE)      // 100352

#define Tt   6
#define Rr   8
#define RR2  72

// Effective weight, K-permuted: row index = tap*128 + c  (tap = kh*3+kw)
__device__ __align__(16) float g_W[Dd * OO];

// ---------------------------------------------------------------------------
// Kernel 1: precompute W_eff. Grid (36, 4): 32-d x 64-o tiles. 256 threads.
// ---------------------------------------------------------------------------
__global__ void precompute_w(const float* __restrict__ S1s,
                             const float* __restrict__ U1s,
                             const float* __restrict__ U2s,
                             const float* __restrict__ S2s) {
    __shared__ float sS1[32][8];    // S1s[t, d0+.., r]
    __shared__ float sU1[8][64];    // U1s[t, r, o0+..]
    __shared__ float sU2[72][32];   // U2s[t, r2, d0+..]
    __shared__ float sS2[72][64];   // S2s[t, r2, o0+..]

    const int tid = threadIdx.x;
    const int d0 = blockIdx.x * 32;
    const int o0 = blockIdx.y * 64;

    const int dd = tid & 31;          // local d this thread owns
    const int og = (tid >> 5) * 8;    // local o base (8 outputs)

    float acc[8];
#pragma unroll
    for (int j = 0; j < 8; j++) acc[j] = 0.f;

    for (int t = 0; t < Tt; t++) {
        {   // sS1: 32*8 = 256 elems
            int row = tid >> 3, col = tid & 7;
            sS1[row][col] = S1s[(t * Dd + d0 + row) * Rr + col];
        }
#pragma unroll
        for (int i = 0; i < 2; i++) {   // sU1: 512 elems
            int idx = tid + i * 256;
            int r = idx >> 6, o = idx & 63;
            sU1[r][o] = U1s[(t * Rr + r) * OO + o0 + o];
        }
#pragma unroll
        for (int i = 0; i < 9; i++) {   // sU2: 2304 elems
            int idx = tid + i * 256;
            int r2 = idx >> 5, d = idx & 31;
            sU2[r2][d] = U2s[(t * RR2 + r2) * Dd + d0 + d];
        }
#pragma unroll
        for (int i = 0; i < 18; i++) {  // sS2: 4608 elems
            int idx = tid + i * 256;
            int r2 = idx >> 6, o = idx & 63;
            sS2[r2][o] = S2s[(t * RR2 + r2) * OO + o0 + o];
        }
        __syncthreads();

#pragma unroll
        for (int r = 0; r < Rr; r++) {
            float a = sS1[dd][r];
#pragma unroll
            for (int j = 0; j < 8; j++) acc[j] += a * sU1[r][og + j];
        }
        for (int r2 = 0; r2 < RR2; r2++) {
            float a = sU2[r2][dd];
#pragma unroll
            for (int j = 0; j < 8; j++) acc[j] += a * sS2[r2][og + j];
        }
        __syncthreads();
    }

    // scatter-store with (tap, c) row permutation; scale by 1/T
    const int d   = d0 + dd;
    const int c   = d / 9;
    const int tap = d - 9 * c;
    float* wrow = &g_W[(tap * 128 + c) * OO + o0 + og];
#pragma unroll
    for (int j = 0; j < 8; j++) wrow[j] = acc[j] * (1.0f / 6.0f);
}

// ---------------------------------------------------------------------------
// Kernel 2: implicit-GEMM conv.
// M = 100352 pixels, N = 256 channels, K = 1152 (ordered tap*128 + c).
// BM=128, BN=128, BK=16; 256 threads; 8x8 micro-tile per thread.
// Grid (784, 2).
// ---------------------------------------------------------------------------
__global__ __launch_bounds__(256, 2)
void conv_main(const float* __restrict__ x,
               const float* __restrict__ bias,
               float* __restrict__ out) {
    __shared__ float As[2][16][128];   // [buf][k][pixel]
    __shared__ float Bs[2][16][128];   // [buf][k][ochan]

    const int tid = threadIdx.x;
    const int bm0 = blockIdx.x * 128;
    const int bn0 = blockIdx.y * 128;

    // --- per-thread A-load geometry (fixed pixel per thread) ---
    const int ml = tid & 127;                 // pixel slot this thread fills
    const int m  = bm0 + ml;                  // global pixel id
    const int bpix = m / PLANE;
    const int rem  = m - bpix * PLANE;
    const int ohp  = rem / WW;
    const int owp  = rem - ohp * WW;
    const float* xb = x + (size_t)bpix * (Cc * PLANE);
    const int klbase = tid >> 7;              // 0 or 1: k rows {klbase, klbase+2, ...}

    // Hoisted im2col geometry: per-tap spatial offset + validity (loop-invariant).
    int  tapOff[9];
    bool tapOk[9];
#pragma unroll
    for (int tap = 0; tap < 9; tap++) {
        const int kh = tap / 3;
        const int kw = tap - 3 * kh;
        const int ih = ohp + kh - 1;
        const int iw = owp + kw - 1;
        tapOk[tap]  = ((unsigned)ih < HH) && ((unsigned)iw < WW);
        tapOff[tap] = ih * WW + iw;
    }

    // --- compute-phase micro-tile coords ---
    const int tx = tid & 15;     // pixel group
    const int ty = tid >> 4;     // channel group

    float acc[8][8];
#pragma unroll
    for (int i = 0; i < 8; i++)
#pragma unroll
        for (int j = 0; j < 8; j++) acc[i][j] = 0.f;

    float  ra[8];
    float4 rb[2];

    // k-tile kt covers K rows [kt*16, kt*16+16): tap = kt>>3 constant per tile.
    auto loadA = [&](int kt) {
        const int tap = kt >> 3;
        const bool valid = tapOk[tap];
        const float* p = xb + ((kt & 7) * 16 + klbase) * PLANE + tapOff[tap];
#pragma unroll
        for (int i = 0; i < 8; i++) {
            float v = 0.f;
            if (valid) v = p[(2 * i) * PLANE];
            ra[i] = v;
        }
    };
    auto loadB = [&](int kt) {
        const float4* w4 = reinterpret_cast<const float4*>(g_W + (size_t)(kt * 16) * OO + bn0);
#pragma unroll
        for (int i = 0; i < 2; i++) {
            int f  = tid + i * 256;
            int kl = f >> 5;
            int o4 = f & 31;
            rb[i] = w4[kl * 64 + o4];   // row stride = 256 floats = 64 float4
        }
    };
    auto storeAB = [&](int buf) {
#pragma unroll
        for (int i = 0; i < 8; i++)
            As[buf][klbase + 2 * i][ml] = ra[i];
#pragma unroll
        for (int i = 0; i < 2; i++) {
            int f  = tid + i * 256;
            int kl = f >> 5;
            int o4 = f & 31;
            reinterpret_cast<float4*>(&Bs[buf][kl][0])[o4] = rb[i];
        }
    };

    loadA(0); loadB(0);
    storeAB(0);
    __syncthreads();

    int bufc = 0;
#pragma unroll 1
    for (int kt = 0; kt < 72; kt++) {
        if (kt < 71) { loadA(kt + 1); loadB(kt + 1); }

#pragma unroll
        for (int k = 0; k < 16; k++) {
            const float4* a4 = reinterpret_cast<const float4*>(&As[bufc][k][0]);
            const float4* b4 = reinterpret_cast<const float4*>(&Bs[bufc][k][0]);
            float4 a0 = a4[tx], a1 = a4[tx + 16];
            float4 b0 = b4[ty], b1 = b4[ty + 16];
            float av[8] = {a0.x, a0.y, a0.z, a0.w, a1.x, a1.y, a1.z, a1.w};
            float bv[8] = {b0.x, b0.y, b0.z, b0.w, b1.x, b1.y, b1.z, b1.w};
#pragma unroll
            for (int i = 0; i < 8; i++)
#pragma unroll
                for (int j = 0; j < 8; j++)
                    acc[i][j] += av[i] * bv[j];
        }

        if (kt < 71) {
            storeAB(bufc ^ 1);
            __syncthreads();
            bufc ^= 1;
        }
    }

    // --- epilogue: out[b][o][p], p = oh*56+ow; bias added twice per reference ---
#pragma unroll
    for (int ii = 0; ii < 2; ii++) {
        const int n0 = bm0 + tx * 4 + ii * 64;      // 4 consecutive pixels, same image
        const int b2 = n0 / PLANE;
        const int p2 = n0 - b2 * PLANE;
#pragma unroll
        for (int jj = 0; jj < 2; jj++) {
#pragma unroll
            for (int j = 0; j < 4; j++) {
                const int o = bn0 + ty * 4 + jj * 64 + j;
                const float bv = 2.0f * bias[o];
                const int col = jj * 4 + j;
                float4 v;
                v.x = acc[ii * 4 + 0][col] + bv;
                v.y = acc[ii * 4 + 1][col] + bv;
                v.z = acc[ii * 4 + 2][col] + bv;
                v.w = acc[ii * 4 + 3][col] + bv;
                *reinterpret_cast<float4*>(out + (size_t)(b2 * OO + o) * PLANE + p2) = v;
            }
        }
    }
}

// ---------------------------------------------------------------------------
extern "C" void kernel_launch(void* const* d_in, const int* in_sizes, int n_in,
                              void* d_out, int out_size) {
    const float* x    = (const float*)d_in[0];
    const float* S1s  = (const float*)d_in[1];
    const float* U1s  = (const float*)d_in[2];
    const float* U2s  = (const float*)d_in[3];
    const float* S2s  = (const float*)d_in[4];
    const float* bias = (const float*)d_in[5];
    float* out = (float*)d_out;

    precompute_w<<<dim3(36, 4), 256>>>(S1s, U1s, U2s, S2s);
    conv_main<<<dim3(784, 2), 256>>>(x, bias, out);
}

// round 6
// speedup vs baseline: 4.2705x; 4.2705x over previous
#include <cuda_runtime.h>
#include <cuda_fp16.h>
#include <cstdint>

// ---------------------------------------------------------------------------
// SKConv2d via mma.sync (fp16 in / fp32 acc), portable to base sm_100:
//   out = im2col(x) @ W_eff + 2*bias
//   W_eff[d,o] = (1/T) * sum_t ( S1s[t] @ U1s[t] + U2s[t]^T @ S2s[t] )
// Kernel 1: build W transposed to [o][k] fp16, k = tap*128 + c.
// Kernel 2: implicit GEMM, BM=128, BN=128, BK=32, 8 warps (2Mx4N),
//           warp tile 64x32 via m16n8k16, double-buffered smem + ldmatrix.
// ---------------------------------------------------------------------------

#define HH    56
#define WWd   56
#define Cc    128
#define OO    256
#define KK    1152
#define PLANE 3136
#define NN    100352
#define Tt    6
#define Rr    8
#define RR2   72

#define BM    128
#define BK    32
#define NCHUNK 36          // 1152/32 ; tap = kt>>2

// W transposed fp16: g_Wh[o*KK + tap*128 + c]
__device__ __align__(16) __half g_Wh[OO * KK];

// ---------------------------------------------------------------------------
__device__ __forceinline__ uint32_t smem_u32(const void* p) {
    uint32_t a;
    asm("{ .reg .u64 t; cvta.to.shared.u64 t, %1; cvt.u32.u64 %0, t; }" : "=r"(a) : "l"(p));
    return a;
}
__device__ __forceinline__ uint32_t swz(uint32_t off) {   // 64B-row swizzle
    return off ^ ((off >> 3) & 0x30);
}
// pack two fp32 -> half2 bits; f0 -> low half (lower address), f1 -> high half
__device__ __forceinline__ uint32_t pack_h2(float f0, float f1) {
    uint32_t r;
    asm("cvt.rn.f16x2.f32 %0, %1, %2;" : "=r"(r) : "f"(f1), "f"(f0));
    return r;
}
#define STS128V(addr, a, b, c, d) \
    asm volatile("st.shared.v4.b32 [%0], {%1,%2,%3,%4};" :: "r"(addr), "r"(a), "r"(b), "r"(c), "r"(d) : "memory")
#define LDSM_X4(r0, r1, r2, r3, addr) \
    asm volatile("ldmatrix.sync.aligned.m8n8.x4.shared.b16 {%0,%1,%2,%3}, [%4];" \
        : "=r"(r0), "=r"(r1), "=r"(r2), "=r"(r3) : "r"(addr))
#define MMA16816(d, a0, a1, a2, a3, b0, b1)                                   \
    asm volatile("mma.sync.aligned.m16n8k16.row.col.f32.f16.f16.f32 "         \
        "{%0,%1,%2,%3}, {%4,%5,%6,%7}, {%8,%9}, {%0,%1,%2,%3};"               \
        : "+f"((d)[0]), "+f"((d)[1]), "+f"((d)[2]), "+f"((d)[3])              \
        : "r"(a0), "r"(a1), "r"(a2), "r"(a3), "r"(b0), "r"(b1))

// ---------------------------------------------------------------------------
// Kernel 1: precompute W_eff -> g_Wh[o][tap*128+c] fp16.
// Grid (36, 4): 32-d x 64-o tiles. 256 threads.
// ---------------------------------------------------------------------------
__global__ void precompute_w(const float* __restrict__ S1s,
                             const float* __restrict__ U1s,
                             const float* __restrict__ U2s,
                             const float* __restrict__ S2s) {
    __shared__ float sS1[32][8];
    __shared__ float sU1[8][64];
    __shared__ float sU2[72][32];
    __shared__ float sS2[72][64];

    const int tid = threadIdx.x;
    const int d0 = blockIdx.x * 32;
    const int o0 = blockIdx.y * 64;
    const int dd = tid & 31;
    const int og = (tid >> 5) * 8;

    float acc[8];
#pragma unroll
    for (int j = 0; j < 8; j++) acc[j] = 0.f;

    for (int t = 0; t < Tt; t++) {
        {   int row = tid >> 3, col = tid & 7;
            sS1[row][col] = S1s[(t * KK + d0 + row) * Rr + col]; }
#pragma unroll
        for (int i = 0; i < 2; i++) {
            int idx = tid + i * 256; int r = idx >> 6, o = idx & 63;
            sU1[r][o] = U1s[(t * Rr + r) * OO + o0 + o]; }
#pragma unroll
        for (int i = 0; i < 9; i++) {
            int idx = tid + i * 256; int r2 = idx >> 5, d = idx & 31;
            sU2[r2][d] = U2s[(t * RR2 + r2) * KK + d0 + d]; }
#pragma unroll
        for (int i = 0; i < 18; i++) {
            int idx = tid + i * 256; int r2 = idx >> 6, o = idx & 63;
            sS2[r2][o] = S2s[(t * RR2 + r2) * OO + o0 + o]; }
        __syncthreads();

#pragma unroll
        for (int r = 0; r < Rr; r++) {
            float a = sS1[dd][r];
#pragma unroll
            for (int j = 0; j < 8; j++) acc[j] += a * sU1[r][og + j];
        }
        for (int r2 = 0; r2 < RR2; r2++) {
            float a = sU2[r2][dd];
#pragma unroll
            for (int j = 0; j < 8; j++) acc[j] += a * sS2[r2][og + j];
        }
        __syncthreads();
    }

    const int d   = d0 + dd;
    const int c   = d / 9;
    const int tap = d - 9 * c;
    const int krow = tap * 128 + c;
#pragma unroll
    for (int j = 0; j < 8; j++)
        g_Wh[(o0 + og + j) * KK + krow] = __float2half_rn(acc[j] * (1.0f / 6.0f));
}

// ---------------------------------------------------------------------------
// Kernel 2: mma.sync implicit GEMM conv. Grid (784, 2), block 256.
// ---------------------------------------------------------------------------
__global__ __launch_bounds__(256)
void conv_mma(const float* __restrict__ x,
              const float* __restrict__ bias,
              float* __restrict__ out) {
    // [buf][row(128)][32 halves] : 64B rows, swizzled
    __shared__ __align__(16) __half As[2][BM * BK];
    __shared__ __align__(16) __half Bs[2][128 * BK];

    const int tid  = threadIdx.x;
    const int lane = tid & 31;
    const int wid  = tid >> 5;
    const int wm   = wid & 1;      // 2 warps in M
    const int wn   = wid >> 1;     // 4 warps in N
    const int bm0  = blockIdx.x * BM;
    const int bn0  = blockIdx.y * 128;

    const uint32_t aBase[2] = { smem_u32(As[0]), smem_u32(As[1]) };
    const uint32_t bBase[2] = { smem_u32(Bs[0]), smem_u32(Bs[1]) };

    // ---- per-thread A-load geometry: pixel = tid&127, channel half = tid>>7 ----
    const int ml  = tid & 127;
    const int chb = (tid >> 7) * 16;          // channel sub-base within chunk
    const int m   = bm0 + ml;
    const int b   = m / PLANE;
    const int rem = m - b * PLANE;
    const int ohp = rem / WWd;
    const int owp = rem - ohp * WWd;
    const float* xb = x + (size_t)b * (Cc * PLANE);

    int  tapOff[9];
    bool tapOk[9];
#pragma unroll
    for (int tap = 0; tap < 9; tap++) {
        const int kh = tap / 3, kw = tap - 3 * kh;
        const int ih = ohp + kh - 1, iw = owp + kw - 1;
        tapOk[tap]  = ((unsigned)ih < HH) && ((unsigned)iw < WWd);
        tapOff[tap] = ih * WWd + iw;
    }

    float acc[4][4][4];
#pragma unroll
    for (int i = 0; i < 4; i++)
#pragma unroll
        for (int j = 0; j < 4; j++)
#pragma unroll
            for (int q = 0; q < 4; q++) acc[i][j][q] = 0.f;

    uint32_t ra[8];      // staged A halves (16 channels = 8 half2)
    uint4    rb[2];      // staged B (2 x 16B)

    auto loadA = [&](int kt) {
        const int tap = kt >> 2;
        const bool ok = tapOk[tap];
        const float* p = xb + tapOff[tap] + (size_t)((kt & 3) * 32 + chb) * PLANE;
#pragma unroll
        for (int q = 0; q < 8; q++) {
            float f0 = 0.f, f1 = 0.f;
            if (ok) { f0 = p[(2 * q) * PLANE]; f1 = p[(2 * q + 1) * PLANE]; }
            ra[q] = pack_h2(f0, f1);
        }
    };
    auto loadB = [&](int kt) {
        const int k0 = kt * BK;
        const uint4* w = reinterpret_cast<const uint4*>(g_Wh);
#pragma unroll
        for (int i = 0; i < 2; i++) {
            int f = tid + i * 256;                  // 512 chunks: 128 rows x 4
            int n = f >> 2, ck = f & 3;
            rb[i] = w[((bn0 + n) * KK + k0 + ck * 8) >> 3];   // FIX: + bn0
        }
    };
    auto storeAB = [&](int buf) {
        const uint32_t a0 = aBase[buf] + swz(ml * 64 + chb * 2);
        STS128V(a0,      ra[0], ra[1], ra[2], ra[3]);
        const uint32_t a1 = aBase[buf] + swz(ml * 64 + chb * 2 + 16);
        STS128V(a1,      ra[4], ra[5], ra[6], ra[7]);
#pragma unroll
        for (int i = 0; i < 2; i++) {
            int f = tid + i * 256;
            int n = f >> 2, ck = f & 3;
            const uint32_t d = bBase[buf] + swz(n * 64 + ck * 16);
            STS128V(d, rb[i].x, rb[i].y, rb[i].z, rb[i].w);
        }
    };

    loadA(0); loadB(0);
    storeAB(0);
    __syncthreads();

    int buf = 0;
#pragma unroll 1
    for (int kt = 0; kt < NCHUNK; kt++) {
        if (kt < NCHUNK - 1) { loadA(kt + 1); loadB(kt + 1); }

#pragma unroll
        for (int ks = 0; ks < 2; ks++) {
            const int k0 = ks * 16;
            uint32_t af[4][4], bf[4][2];
            // A: 4 m-tiles of 16; lane -> row m0+(lane&15), col k0+(lane>>4)*8
#pragma unroll
            for (int i = 0; i < 4; i++) {
                const int mr = wm * 64 + i * 16 + (lane & 15);
                const int kc = k0 + (lane >> 4) * 8;
                LDSM_X4(af[i][0], af[i][1], af[i][2], af[i][3],
                        aBase[buf] + swz(mr * 64 + kc * 2));
            }
            // B: 2 x ldmatrix.x4, each covering two 8-wide n-tiles
#pragma unroll
            for (int jj = 0; jj < 2; jj++) {
                const int nr = wn * 32 + jj * 16 + ((lane >> 4) & 1) * 8 + (lane & 7);
                const int kc = k0 + ((lane >> 3) & 1) * 8;
                LDSM_X4(bf[2 * jj][0], bf[2 * jj][1], bf[2 * jj + 1][0], bf[2 * jj + 1][1],
                        bBase[buf] + swz(nr * 64 + kc * 2));
            }
#pragma unroll
            for (int i = 0; i < 4; i++)
#pragma unroll
                for (int j = 0; j < 4; j++)
                    MMA16816(acc[i][j], af[i][0], af[i][1], af[i][2], af[i][3],
                             bf[j][0], bf[j][1]);
        }

        if (kt < NCHUNK - 1) {
            storeAB(buf ^ 1);
            __syncthreads();
            buf ^= 1;
        }
    }

    // ---- epilogue: thread lane holds rows (l>>2, l>>2+8), cols 2*(l&3)+{0,1} ----
#pragma unroll
    for (int i = 0; i < 4; i++) {
        const int mg0 = bm0 + wm * 64 + i * 16 + (lane >> 2);
        const int b0e = mg0 / PLANE;
        const int p0e = mg0 - b0e * PLANE;
        const int mg1 = mg0 + 8;
        const int b1e = mg1 / PLANE;
        const int p1e = mg1 - b1e * PLANE;
        float* o0 = out + (size_t)b0e * (OO * PLANE) + p0e;
        float* o1 = out + (size_t)b1e * (OO * PLANE) + p1e;
#pragma unroll
        for (int j = 0; j < 4; j++) {
            const int o = bn0 + wn * 32 + j * 8 + (lane & 3) * 2;
            const float bv0 = 2.0f * __ldg(bias + o);
            const float bv1 = 2.0f * __ldg(bias + o + 1);
            o0[(size_t)o * PLANE]       = acc[i][j][0] + bv0;
            o0[(size_t)(o + 1) * PLANE] = acc[i][j][1] + bv1;
            o1[(size_t)o * PLANE]       = acc[i][j][2] + bv0;
            o1[(size_t)(o + 1) * PLANE] = acc[i][j][3] + bv1;
        }
    }
}

// ---------------------------------------------------------------------------
extern "C" void kernel_launch(void* const* d_in, const int* in_sizes, int n_in,
                              void* d_out, int out_size) {
    const float* x    = (const float*)d_in[0];
    const float* S1s  = (const float*)d_in[1];
    const float* U1s  = (const float*)d_in[2];
    const float* U2s  = (const float*)d_in[3];
    const float* S2s  = (const float*)d_in[4];
    const float* bias = (const float*)d_in[5];
    float* out = (float*)d_out;

    precompute_w<<<dim3(36, 4), 256>>>(S1s, U1s, U2s, S2s);
    conv_mma<<<dim3(784, 2), 256>>>(x, bias, out);
}